// round 4
// baseline (speedup 1.0000x reference)
#include <cuda_runtime.h>
#include <math.h>

// Problem constants
#define BSZ   4
#define N1    4096
#define N2    256
#define DIM   1024
#define HEADS 16
#define DH    64
#define INNER 1024
#define EPS   1e-5f

// ---------------------------------------------------------------------------
// Scratch (device globals; no runtime allocation allowed)
// ---------------------------------------------------------------------------
__device__ float g_xn[BSZ * N1 * DIM];          // 64 MB  : layernorm(x)
__device__ float g_ln[BSZ * N2 * DIM];          //  4 MB  : layernorm(latents)
__device__ float g_q [BSZ * N2 * INNER];        //  4 MB  : q = ln @ Wq
__device__ float g_kv[BSZ * N1 * 2 * INNER];    // 128 MB : kv = xn @ Wkv
__device__ float g_ao[BSZ * N2 * INNER];        //  4 MB  : attention output

// ---------------------------------------------------------------------------
// Block reduction helper (256 threads = 8 warps)
// ---------------------------------------------------------------------------
__device__ __forceinline__ float block_sum_256(float v, float* sbuf) {
    #pragma unroll
    for (int off = 16; off > 0; off >>= 1)
        v += __shfl_xor_sync(0xffffffffu, v, off);
    int w = threadIdx.x >> 5;
    if ((threadIdx.x & 31) == 0) sbuf[w] = v;
    __syncthreads();
    float r = (threadIdx.x < 8) ? sbuf[threadIdx.x] : 0.0f;
    #pragma unroll
    for (int off = 4; off > 0; off >>= 1)
        r += __shfl_xor_sync(0xffffffffu, r, off);
    if (threadIdx.x == 0) sbuf[0] = r;
    __syncthreads();
    float out = sbuf[0];
    __syncthreads();
    return out;
}

// ---------------------------------------------------------------------------
// LayerNorm over last dim (1024). One block per row, 256 threads, float4.
// ---------------------------------------------------------------------------
__global__ void ln_kernel(const float* __restrict__ x,
                          const float* __restrict__ w,
                          const float* __restrict__ b,
                          float* __restrict__ y) {
    __shared__ float sbuf[8];
    size_t row = blockIdx.x;
    int t = threadIdx.x;

    const float4 v = ((const float4*)(x + row * DIM))[t];
    float s = v.x + v.y + v.z + v.w;
    float tot = block_sum_256(s, sbuf);
    float mean = tot * (1.0f / DIM);

    float dx = v.x - mean, dy = v.y - mean, dz = v.z - mean, dw = v.w - mean;
    float sq = dx * dx + dy * dy + dz * dz + dw * dw;
    float vtot = block_sum_256(sq, sbuf);
    float inv = rsqrtf(vtot * (1.0f / DIM) + EPS);

    const float4 wv = ((const float4*)w)[t];
    const float4 bv = ((const float4*)b)[t];
    float4 o;
    o.x = dx * inv * wv.x + bv.x;
    o.y = dy * inv * wv.y + bv.y;
    o.z = dz * inv * wv.z + bv.z;
    o.w = dw * inv * wv.w + bv.w;
    ((float4*)(y + row * DIM))[t] = o;
}

// ---------------------------------------------------------------------------
// SGEMM: C[M,N] = A[M,K] @ B[K,N], all row-major, M%128==0, N%128==0, K%8==0.
// 128x128 tile, BK=8, 256 threads, 8x8 register micro-tile.
// ---------------------------------------------------------------------------
__global__ void __launch_bounds__(256, 2)
sgemm_kernel(const float* __restrict__ A, const float* __restrict__ Bm,
             float* __restrict__ C, int M, int N, int K) {
    __shared__ float As[8][128];
    __shared__ float Bs[8][128];

    const int bn = blockIdx.x * 128;
    const int bm = blockIdx.y * 128;
    const int tid = threadIdx.x;
    const int tx = tid & 15;
    const int ty = tid >> 4;

    float acc[8][8];
    #pragma unroll
    for (int i = 0; i < 8; i++)
        #pragma unroll
        for (int j = 0; j < 8; j++) acc[i][j] = 0.0f;

    const int arow = tid >> 1;          // 0..127
    const int acol = (tid & 1) * 4;     // 0 or 4
    const int brow = tid >> 5;          // 0..7
    const int bcol = (tid & 31) * 4;    // 0..124

    const float* Aptr = A + (size_t)(bm + arow) * K + acol;
    const float* Bptr = Bm + (size_t)brow * N + bn + bcol;

    for (int k0 = 0; k0 < K; k0 += 8) {
        float4 av = *(const float4*)(Aptr + k0);
        float4 bv = *(const float4*)(Bptr + (size_t)k0 * N);
        As[acol + 0][arow] = av.x;
        As[acol + 1][arow] = av.y;
        As[acol + 2][arow] = av.z;
        As[acol + 3][arow] = av.w;
        *(float4*)&Bs[brow][bcol] = bv;
        __syncthreads();

        #pragma unroll
        for (int kk = 0; kk < 8; kk++) {
            float ra[8], rb[8];
            #pragma unroll
            for (int i = 0; i < 8; i++) ra[i] = As[kk][ty * 8 + i];
            #pragma unroll
            for (int j = 0; j < 8; j++) rb[j] = Bs[kk][tx * 8 + j];
            #pragma unroll
            for (int i = 0; i < 8; i++)
                #pragma unroll
                for (int j = 0; j < 8; j++)
                    acc[i][j] += ra[i] * rb[j];
        }
        __syncthreads();
    }

    #pragma unroll
    for (int i = 0; i < 8; i++) {
        float* crow = C + (size_t)(bm + ty * 8 + i) * N + bn + tx * 8;
        *(float4*)(crow + 0) = make_float4(acc[i][0], acc[i][1], acc[i][2], acc[i][3]);
        *(float4*)(crow + 4) = make_float4(acc[i][4], acc[i][5], acc[i][6], acc[i][7]);
    }
}

// ---------------------------------------------------------------------------
// Fused flash-style attention per (b, h), 64-query tile, full n1 sweep.
// Q modulation (AdaLN) + attn scale folded into Q tile load.
// grid = (BSZ*HEADS, N2/64), block = 256 threads (16x16 -> 4x4 micro-tiles).
// ---------------------------------------------------------------------------
__global__ void __launch_bounds__(256, 2)
attn_kernel(const float* __restrict__ q,
            const float* __restrict__ kv,
            const float* __restrict__ shift,
            const float* __restrict__ scale,
            float* __restrict__ out) {
    __shared__ float Qs[64][64];   // [qrow][d]
    __shared__ float KV[64][64];   // K: transposed [d][key]; V: [key][d]
    __shared__ float Ps[64][64];   // [qrow][key]

    const int bh = blockIdx.x;
    const int b  = bh >> 4;
    const int h  = bh & 15;
    const int qt = blockIdx.y;

    const int tid = threadIdx.x;
    const int tx = tid & 15;
    const int ty = tid >> 4;
    const int lrow = tid >> 4;         // 0..15 base row for tiled loads
    const int lc4  = (tid & 15) * 4;   // 0..60 col (float4)

    const float sc = 1.0f + scale[b * HEADS + h];
    const float sh = shift[b * HEADS + h];
    const float qmul = 0.125f;         // 1/sqrt(64)

    // Load + modulate Q tile (64 queries x 64 dims)
    #pragma unroll
    for (int r = 0; r < 4; r++) {
        int row = lrow + 16 * r;
        const float4 v = *(const float4*)(q + ((size_t)(b * N2 + qt * 64 + row)) * INNER
                                            + h * DH + lc4);
        Qs[row][lc4 + 0] = (v.x * sc + sh) * qmul;
        Qs[row][lc4 + 1] = (v.y * sc + sh) * qmul;
        Qs[row][lc4 + 2] = (v.z * sc + sh) * qmul;
        Qs[row][lc4 + 3] = (v.w * sc + sh) * qmul;
    }

    float m[4], l[4], o[4][4];
    #pragma unroll
    for (int i = 0; i < 4; i++) {
        m[i] = -INFINITY;
        l[i] = 0.0f;
        #pragma unroll
        for (int j = 0; j < 4; j++) o[i][j] = 0.0f;
    }

    for (int kt = 0; kt < N1 / 64; kt++) {
        __syncthreads();  // previous V reads (and initial Q writes) complete

        // Load K tile transposed: KV[d][key]
        #pragma unroll
        for (int r = 0; r < 4; r++) {
            int key = lrow + 16 * r;
            const float4 v = *(const float4*)(kv + ((size_t)(b * N1 + kt * 64 + key)) * (2 * INNER)
                                                + h * DH + lc4);
            KV[lc4 + 0][key] = v.x;
            KV[lc4 + 1][key] = v.y;
            KV[lc4 + 2][key] = v.z;
            KV[lc4 + 3][key] = v.w;
        }
        __syncthreads();

        // S = Qmod @ K^T (4x4 per thread)
        float s[4][4];
        #pragma unroll
        for (int i = 0; i < 4; i++)
            #pragma unroll
            for (int j = 0; j < 4; j++) s[i][j] = 0.0f;

        #pragma unroll 8
        for (int d = 0; d < 64; d++) {
            float ra[4], rb[4];
            #pragma unroll
            for (int i = 0; i < 4; i++) ra[i] = Qs[4 * ty + i][d];
            #pragma unroll
            for (int j = 0; j < 4; j++) rb[j] = KV[d][4 * tx + j];
            #pragma unroll
            for (int i = 0; i < 4; i++)
                #pragma unroll
                for (int j = 0; j < 4; j++)
                    s[i][j] += ra[i] * rb[j];
        }

        // Online softmax update (row groups = 16 contiguous lanes)
        #pragma unroll
        for (int i = 0; i < 4; i++) {
            float rmax = s[i][0];
            #pragma unroll
            for (int j = 1; j < 4; j++) rmax = fmaxf(rmax, s[i][j]);
            #pragma unroll
            for (int off = 8; off > 0; off >>= 1)
                rmax = fmaxf(rmax, __shfl_xor_sync(0xffffffffu, rmax, off, 16));

            float mnew = fmaxf(m[i], rmax);
            float alpha = __expf(m[i] - mnew);
            float psum = 0.0f;
            #pragma unroll
            for (int j = 0; j < 4; j++) {
                float p = __expf(s[i][j] - mnew);
                s[i][j] = p;
                psum += p;
            }
            #pragma unroll
            for (int off = 8; off > 0; off >>= 1)
                psum += __shfl_xor_sync(0xffffffffu, psum, off, 16);

            l[i] = l[i] * alpha + psum;
            m[i] = mnew;
            #pragma unroll
            for (int j = 0; j < 4; j++) o[i][j] *= alpha;
            #pragma unroll
            for (int j = 0; j < 4; j++) Ps[4 * ty + i][4 * tx + j] = s[i][j];
        }
        __syncthreads();  // Ps written, K reads done

        // Load V tile natural layout: KV[key][d]
        #pragma unroll
        for (int r = 0; r < 4; r++) {
            int key = lrow + 16 * r;
            const float4 v = *(const float4*)(kv + ((size_t)(b * N1 + kt * 64 + key)) * (2 * INNER)
                                                + INNER + h * DH + lc4);
            *(float4*)&KV[key][lc4] = v;
        }
        __syncthreads();

        // O += P @ V
        #pragma unroll 8
        for (int kk = 0; kk < 64; kk++) {
            float pa[4], vb[4];
            #pragma unroll
            for (int i = 0; i < 4; i++) pa[i] = Ps[4 * ty + i][kk];
            #pragma unroll
            for (int j = 0; j < 4; j++) vb[j] = KV[kk][4 * tx + j];
            #pragma unroll
            for (int i = 0; i < 4; i++)
                #pragma unroll
                for (int j = 0; j < 4; j++)
                    o[i][j] += pa[i] * vb[j];
        }
    }

    // Epilogue: normalize and write (b, n2, h, dh) flattened to (B*N2, INNER)
    #pragma unroll
    for (int i = 0; i < 4; i++) {
        float invl = 1.0f / l[i];
        int row = qt * 64 + 4 * ty + i;
        #pragma unroll
        for (int j = 0; j < 4; j++) {
            out[((size_t)(b * N2 + row)) * INNER + h * DH + 4 * tx + j] = o[i][j] * invl;
        }
    }
}

// ---------------------------------------------------------------------------
// Launcher
// ---------------------------------------------------------------------------
extern "C" void kernel_launch(void* const* d_in, const int* in_sizes, int n_in,
                              void* d_out, int out_size) {
    const float* x       = (const float*)d_in[0];
    const float* latents = (const float*)d_in[1];
    const float* shift   = (const float*)d_in[2];
    const float* scale   = (const float*)d_in[3];
    const float* ln1_w   = (const float*)d_in[4];
    const float* ln1_b   = (const float*)d_in[5];
    const float* ln2_w   = (const float*)d_in[6];
    const float* ln2_b   = (const float*)d_in[7];
    const float* Wq      = (const float*)d_in[8];
    const float* Wkv     = (const float*)d_in[9];
    const float* Wout    = (const float*)d_in[10];
    float* out           = (float*)d_out;

    float *xn, *ln, *q, *kv, *ao;
    cudaGetSymbolAddress((void**)&xn, g_xn);
    cudaGetSymbolAddress((void**)&ln, g_ln);
    cudaGetSymbolAddress((void**)&q,  g_q);
    cudaGetSymbolAddress((void**)&kv, g_kv);
    cudaGetSymbolAddress((void**)&ao, g_ao);

    // 1) LayerNorms
    ln_kernel<<<BSZ * N1, 256>>>(x, ln1_w, ln1_b, xn);
    ln_kernel<<<BSZ * N2, 256>>>(latents, ln2_w, ln2_b, ln);

    // 2) q = ln @ Wq   (1024 x 1024 x 1024)
    sgemm_kernel<<<dim3(INNER / 128, (BSZ * N2) / 128), 256>>>(ln, Wq, q,
                                                               BSZ * N2, INNER, DIM);

    // 3) kv = xn @ Wkv (16384 x 2048 x 1024)  — dominant GEMM
    sgemm_kernel<<<dim3((2 * INNER) / 128, (BSZ * N1) / 128), 256>>>(xn, Wkv, kv,
                                                                     BSZ * N1, 2 * INNER, DIM);

    // 4) fused modulation + attention
    attn_kernel<<<dim3(BSZ * HEADS, N2 / 64), 256>>>(q, kv, shift, scale, ao);

    // 5) out = ao @ Wout (1024 x 1024 x 1024)
    sgemm_kernel<<<dim3(DIM / 128, (BSZ * N2) / 128), 256>>>(ao, Wout, out,
                                                             BSZ * N2, DIM, INNER);
}

// round 6
// speedup vs baseline: 2.0279x; 2.0279x over previous
#include <cuda_runtime.h>
#include <cuda_bf16.h>
#include <cstdint>
#include <math.h>

// Problem constants
#define BSZ   4
#define N1    4096
#define N2    256
#define DIM   1024
#define HEADS 16
#define DH    64
#define INNER 1024
#define EPS   1e-5f

// ---------------------------------------------------------------------------
// Scratch (device globals; no runtime allocation allowed)
// ---------------------------------------------------------------------------
__device__ float g_xn[BSZ * N1 * DIM];          // 64 MB  : layernorm(x)
__device__ float g_ln[BSZ * N2 * DIM];          //  4 MB  : layernorm(latents)
__device__ float g_q [BSZ * N2 * INNER];        //  4 MB  : q = ln @ Wq
__device__ float g_kv[BSZ * N1 * 2 * INNER];    // 128 MB : kv = xn @ Wkv
__device__ float g_ao[BSZ * N2 * INNER];        //  4 MB  : attention output
__device__ float g_wqT [INNER * DIM];           //  4 MB  : Wq^T   [N,K]
__device__ float g_wkvT[2 * INNER * DIM];       //  8 MB  : Wkv^T  [N,K]
__device__ float g_woT [DIM * INNER];           //  4 MB  : Wout^T [N,K]

// ---------------------------------------------------------------------------
// Block reduction helper (256 threads = 8 warps)
// ---------------------------------------------------------------------------
__device__ __forceinline__ float block_sum_256(float v, float* sbuf) {
    #pragma unroll
    for (int off = 16; off > 0; off >>= 1)
        v += __shfl_xor_sync(0xffffffffu, v, off);
    int w = threadIdx.x >> 5;
    if ((threadIdx.x & 31) == 0) sbuf[w] = v;
    __syncthreads();
    float r = (threadIdx.x < 8) ? sbuf[threadIdx.x] : 0.0f;
    #pragma unroll
    for (int off = 4; off > 0; off >>= 1)
        r += __shfl_xor_sync(0xffffffffu, r, off);
    if (threadIdx.x == 0) sbuf[0] = r;
    __syncthreads();
    float out = sbuf[0];
    __syncthreads();
    return out;
}

// ---------------------------------------------------------------------------
// LayerNorm over last dim (1024). One block per row, 256 threads, float4.
// ---------------------------------------------------------------------------
__global__ void ln_kernel(const float* __restrict__ x,
                          const float* __restrict__ w,
                          const float* __restrict__ b,
                          float* __restrict__ y) {
    __shared__ float sbuf[8];
    size_t row = blockIdx.x;
    int t = threadIdx.x;

    const float4 v = ((const float4*)(x + row * DIM))[t];
    float s = v.x + v.y + v.z + v.w;
    float tot = block_sum_256(s, sbuf);
    float mean = tot * (1.0f / DIM);

    float dx = v.x - mean, dy = v.y - mean, dz = v.z - mean, dw = v.w - mean;
    float sq = dx * dx + dy * dy + dz * dz + dw * dw;
    float vtot = block_sum_256(sq, sbuf);
    float inv = rsqrtf(vtot * (1.0f / DIM) + EPS);

    const float4 wv = ((const float4*)w)[t];
    const float4 bv = ((const float4*)b)[t];
    float4 o;
    o.x = dx * inv * wv.x + bv.x;
    o.y = dy * inv * wv.y + bv.y;
    o.z = dz * inv * wv.z + bv.z;
    o.w = dw * inv * wv.w + bv.w;
    ((float4*)(y + row * DIM))[t] = o;
}

// ---------------------------------------------------------------------------
// 32x32 tiled transpose: out[C,R] = in[R,C]^T  (R, C multiples of 32)
// ---------------------------------------------------------------------------
__global__ void transpose_kernel(const float* __restrict__ in,
                                 float* __restrict__ out, int R, int C) {
    __shared__ float t[32][33];
    int c0 = blockIdx.x * 32, r0 = blockIdx.y * 32;
    #pragma unroll
    for (int i = 0; i < 32; i += 8)
        t[threadIdx.y + i][threadIdx.x] =
            in[(size_t)(r0 + threadIdx.y + i) * C + c0 + threadIdx.x];
    __syncthreads();
    #pragma unroll
    for (int i = 0; i < 32; i += 8)
        out[(size_t)(c0 + threadIdx.y + i) * R + r0 + threadIdx.x] =
            t[threadIdx.x][threadIdx.y + i];
}

// ---------------------------------------------------------------------------
// bf16-split tensor-core GEMM: C[M,N] = A[M,K] @ Bt[N,K]^T  (fp32 accuracy)
//
// x = hi + lo (both bf16, exact split); C = Ah*Bh + Ah*Bl + Al*Bh.
// mma.sync.m16n8k16.row.col.f32.bf16.bf16.f32 (sm_80 PTX -> HMMA on sm_103).
// Block tile 128x128, BK=32, 256 threads (8 warps, 2x4 grid, 64x32/warp).
// SMEM: 4 matrices (Ah, Al, Bh, Bl), 128 rows x 16 k-words, row stride 20
// words (conflict-free fragment loads). Single stage, 2 CTAs/SM overlap.
// ---------------------------------------------------------------------------
#define RS 20                       // smem row stride in 32-bit words
#define MATW (128 * RS)             // 2560 words per matrix
#define GT_SMEM (4 * MATW * 4)      // 40960 bytes

__device__ __forceinline__ void mma_bf16(float* c, const uint32_t* a, const uint32_t* b) {
    asm volatile(
        "mma.sync.aligned.m16n8k16.row.col.f32.bf16.bf16.f32 "
        "{%0,%1,%2,%3}, {%4,%5,%6,%7}, {%8,%9}, {%0,%1,%2,%3};"
        : "+f"(c[0]), "+f"(c[1]), "+f"(c[2]), "+f"(c[3])
        : "r"(a[0]), "r"(a[1]), "r"(a[2]), "r"(a[3]), "r"(b[0]), "r"(b[1]));
}

__device__ __forceinline__ uint32_t pack_bf16(float x, float y) {
    __nv_bfloat162 h = __floats2bfloat162_rn(x, y);
    return *reinterpret_cast<uint32_t*>(&h);
}

__global__ void __launch_bounds__(256, 2)
gemm_bf16_kernel(const float* __restrict__ A, const float* __restrict__ Bt,
                 float* __restrict__ C, int M, int N, int K) {
    extern __shared__ uint32_t sh[];
    uint32_t* AH = sh;
    uint32_t* AL = sh + MATW;
    uint32_t* BH = sh + 2 * MATW;
    uint32_t* BL = sh + 3 * MATW;

    const int tid  = threadIdx.x;
    const int lane = tid & 31;
    const int wid  = tid >> 5;
    const int warp_m = wid >> 2;      // 0..1
    const int warp_n = wid & 3;       // 0..3
    const int bm = blockIdx.y * 128;
    const int bn = blockIdx.x * 128;

    // loader mapping: threads 0-127 -> A, 128-255 -> B
    const int matB = tid >> 7;
    const int lt   = tid & 127;
    const int lf   = lt & 7;          // float4 index within 32-K row
    const int lr0  = lt >> 3;         // 0..15, rows lr0 + 16*i
    const float* src = matB ? (Bt + (size_t)bn * K) : (A + (size_t)bm * K);
    uint32_t* dstH = matB ? BH : AH;
    uint32_t* dstL = matB ? BL : AL;

    float acc[4][4][4];
    #pragma unroll
    for (int i = 0; i < 4; i++)
        #pragma unroll
        for (int j = 0; j < 4; j++)
            #pragma unroll
            for (int k = 0; k < 4; k++) acc[i][j][k] = 0.0f;

    const int aoff0 = (warp_m * 64 + (lane >> 2)) * RS + (lane & 3);
    const int boff0 = (warp_n * 32 + (lane >> 2)) * RS + (lane & 3);

    for (int k0 = 0; k0 < K; k0 += 32) {
        __syncthreads();  // previous chunk's mma reads complete

        // ---- load fp32 chunk, split into bf16 hi/lo, store to smem ----
        #pragma unroll
        for (int i = 0; i < 8; i++) {
            int row = lr0 + 16 * i;
            float4 v = *(const float4*)(src + (size_t)row * K + k0 + lf * 4);
            float hx = __bfloat162float(__float2bfloat16_rn(v.x));
            float hy = __bfloat162float(__float2bfloat16_rn(v.y));
            float hz = __bfloat162float(__float2bfloat16_rn(v.z));
            float hw = __bfloat162float(__float2bfloat16_rn(v.w));
            int w = row * RS + lf * 2;
            dstH[w]     = pack_bf16(hx, hy);
            dstH[w + 1] = pack_bf16(hz, hw);
            dstL[w]     = pack_bf16(v.x - hx, v.y - hy);
            dstL[w + 1] = pack_bf16(v.z - hz, v.w - hw);
        }
        __syncthreads();

        // ---- tensor-core MMA phase ----
        #pragma unroll
        for (int ks = 0; ks < 2; ks++) {
            uint32_t bh[4][2], bl[4][2];
            #pragma unroll
            for (int nb = 0; nb < 4; nb++) {
                int wb = boff0 + nb * 8 * RS + ks * 8;
                bh[nb][0] = BH[wb];     bh[nb][1] = BH[wb + 4];
                bl[nb][0] = BL[wb];     bl[nb][1] = BL[wb + 4];
            }
            #pragma unroll
            for (int ma = 0; ma < 4; ma++) {
                int wa = aoff0 + ma * 16 * RS + ks * 8;
                uint32_t ah[4], al[4];
                ah[0] = AH[wa];             ah[1] = AH[wa + 8 * RS];
                ah[2] = AH[wa + 4];         ah[3] = AH[wa + 8 * RS + 4];
                al[0] = AL[wa];             al[1] = AL[wa + 8 * RS];
                al[2] = AL[wa + 4];         al[3] = AL[wa + 8 * RS + 4];
                #pragma unroll
                for (int nb = 0; nb < 4; nb++) {
                    mma_bf16(acc[ma][nb], ah, bh[nb]);
                    mma_bf16(acc[ma][nb], ah, bl[nb]);
                    mma_bf16(acc[ma][nb], al, bh[nb]);
                }
            }
        }
    }

    // ---- epilogue ----
    #pragma unroll
    for (int ma = 0; ma < 4; ma++) {
        int row = bm + warp_m * 64 + ma * 16 + (lane >> 2);
        #pragma unroll
        for (int nb = 0; nb < 4; nb++) {
            int col = bn + warp_n * 32 + nb * 8 + (lane & 3) * 2;
            *(float2*)(C + (size_t)row * N + col) =
                make_float2(acc[ma][nb][0], acc[ma][nb][1]);
            *(float2*)(C + (size_t)(row + 8) * N + col) =
                make_float2(acc[ma][nb][2], acc[ma][nb][3]);
        }
    }
}

// ---------------------------------------------------------------------------
// Fused flash-style attention per (b, h), 64-query tile, full n1 sweep.
// ---------------------------------------------------------------------------
__global__ void __launch_bounds__(256, 2)
attn_kernel(const float* __restrict__ q,
            const float* __restrict__ kv,
            const float* __restrict__ shift,
            const float* __restrict__ scale,
            float* __restrict__ out) {
    __shared__ float Qs[64][64];   // [qrow][d]
    __shared__ float KV[64][64];   // K: transposed [d][key]; V: [key][d]
    __shared__ float Ps[64][64];   // [qrow][key]

    const int bh = blockIdx.x;
    const int b  = bh >> 4;
    const int h  = bh & 15;
    const int qt = blockIdx.y;

    const int tid = threadIdx.x;
    const int tx = tid & 15;
    const int ty = tid >> 4;
    const int lrow = tid >> 4;
    const int lc4  = (tid & 15) * 4;

    const float sc = 1.0f + scale[b * HEADS + h];
    const float sh = shift[b * HEADS + h];
    const float qmul = 0.125f;

    #pragma unroll
    for (int r = 0; r < 4; r++) {
        int row = lrow + 16 * r;
        const float4 v = *(const float4*)(q + ((size_t)(b * N2 + qt * 64 + row)) * INNER
                                            + h * DH + lc4);
        Qs[row][lc4 + 0] = (v.x * sc + sh) * qmul;
        Qs[row][lc4 + 1] = (v.y * sc + sh) * qmul;
        Qs[row][lc4 + 2] = (v.z * sc + sh) * qmul;
        Qs[row][lc4 + 3] = (v.w * sc + sh) * qmul;
    }

    float m[4], l[4], o[4][4];
    #pragma unroll
    for (int i = 0; i < 4; i++) {
        m[i] = -INFINITY;
        l[i] = 0.0f;
        #pragma unroll
        for (int j = 0; j < 4; j++) o[i][j] = 0.0f;
    }

    for (int kt = 0; kt < N1 / 64; kt++) {
        __syncthreads();

        #pragma unroll
        for (int r = 0; r < 4; r++) {
            int key = lrow + 16 * r;
            const float4 v = *(const float4*)(kv + ((size_t)(b * N1 + kt * 64 + key)) * (2 * INNER)
                                                + h * DH + lc4);
            KV[lc4 + 0][key] = v.x;
            KV[lc4 + 1][key] = v.y;
            KV[lc4 + 2][key] = v.z;
            KV[lc4 + 3][key] = v.w;
        }
        __syncthreads();

        float s[4][4];
        #pragma unroll
        for (int i = 0; i < 4; i++)
            #pragma unroll
            for (int j = 0; j < 4; j++) s[i][j] = 0.0f;

        #pragma unroll 8
        for (int d = 0; d < 64; d++) {
            float ra[4], rb[4];
            #pragma unroll
            for (int i = 0; i < 4; i++) ra[i] = Qs[4 * ty + i][d];
            #pragma unroll
            for (int j = 0; j < 4; j++) rb[j] = KV[d][4 * tx + j];
            #pragma unroll
            for (int i = 0; i < 4; i++)
                #pragma unroll
                for (int j = 0; j < 4; j++)
                    s[i][j] += ra[i] * rb[j];
        }

        #pragma unroll
        for (int i = 0; i < 4; i++) {
            float rmax = s[i][0];
            #pragma unroll
            for (int j = 1; j < 4; j++) rmax = fmaxf(rmax, s[i][j]);
            #pragma unroll
            for (int off = 8; off > 0; off >>= 1)
                rmax = fmaxf(rmax, __shfl_xor_sync(0xffffffffu, rmax, off, 16));

            float mnew = fmaxf(m[i], rmax);
            float alpha = __expf(m[i] - mnew);
            float psum = 0.0f;
            #pragma unroll
            for (int j = 0; j < 4; j++) {
                float p = __expf(s[i][j] - mnew);
                s[i][j] = p;
                psum += p;
            }
            #pragma unroll
            for (int off = 8; off > 0; off >>= 1)
                psum += __shfl_xor_sync(0xffffffffu, psum, off, 16);

            l[i] = l[i] * alpha + psum;
            m[i] = mnew;
            #pragma unroll
            for (int j = 0; j < 4; j++) o[i][j] *= alpha;
            #pragma unroll
            for (int j = 0; j < 4; j++) Ps[4 * ty + i][4 * tx + j] = s[i][j];
        }
        __syncthreads();

        #pragma unroll
        for (int r = 0; r < 4; r++) {
            int key = lrow + 16 * r;
            const float4 v = *(const float4*)(kv + ((size_t)(b * N1 + kt * 64 + key)) * (2 * INNER)
                                                + INNER + h * DH + lc4);
            *(float4*)&KV[key][lc4] = v;
        }
        __syncthreads();

        #pragma unroll 8
        for (int kk = 0; kk < 64; kk++) {
            float pa[4], vb[4];
            #pragma unroll
            for (int i = 0; i < 4; i++) pa[i] = Ps[4 * ty + i][kk];
            #pragma unroll
            for (int j = 0; j < 4; j++) vb[j] = KV[kk][4 * tx + j];
            #pragma unroll
            for (int i = 0; i < 4; i++)
                #pragma unroll
                for (int j = 0; j < 4; j++)
                    o[i][j] += pa[i] * vb[j];
        }
    }

    #pragma unroll
    for (int i = 0; i < 4; i++) {
        float invl = 1.0f / l[i];
        int row = qt * 64 + 4 * ty + i;
        #pragma unroll
        for (int j = 0; j < 4; j++) {
            out[((size_t)(b * N2 + row)) * INNER + h * DH + 4 * tx + j] = o[i][j] * invl;
        }
    }
}

// ---------------------------------------------------------------------------
// Launcher
// ---------------------------------------------------------------------------
extern "C" void kernel_launch(void* const* d_in, const int* in_sizes, int n_in,
                              void* d_out, int out_size) {
    const float* x       = (const float*)d_in[0];
    const float* latents = (const float*)d_in[1];
    const float* shift   = (const float*)d_in[2];
    const float* scale   = (const float*)d_in[3];
    const float* ln1_w   = (const float*)d_in[4];
    const float* ln1_b   = (const float*)d_in[5];
    const float* ln2_w   = (const float*)d_in[6];
    const float* ln2_b   = (const float*)d_in[7];
    const float* Wq      = (const float*)d_in[8];
    const float* Wkv     = (const float*)d_in[9];
    const float* Wout    = (const float*)d_in[10];
    float* out           = (float*)d_out;

    float *xn, *ln, *q, *kv, *ao, *wqT, *wkvT, *woT;
    cudaGetSymbolAddress((void**)&xn,   g_xn);
    cudaGetSymbolAddress((void**)&ln,   g_ln);
    cudaGetSymbolAddress((void**)&q,    g_q);
    cudaGetSymbolAddress((void**)&kv,   g_kv);
    cudaGetSymbolAddress((void**)&ao,   g_ao);
    cudaGetSymbolAddress((void**)&wqT,  g_wqT);
    cudaGetSymbolAddress((void**)&wkvT, g_wkvT);
    cudaGetSymbolAddress((void**)&woT,  g_woT);

    // 1) LayerNorms
    ln_kernel<<<BSZ * N1, 256>>>(x, ln1_w, ln1_b, xn);
    ln_kernel<<<BSZ * N2, 256>>>(latents, ln2_w, ln2_b, ln);

    // 2) transpose weights -> [N,K] (K-contiguous "col-major B" operands)
    transpose_kernel<<<dim3(INNER / 32, DIM / 32), dim3(32, 8)>>>(Wq, wqT, DIM, INNER);
    transpose_kernel<<<dim3(2 * INNER / 32, DIM / 32), dim3(32, 8)>>>(Wkv, wkvT, DIM, 2 * INNER);
    transpose_kernel<<<dim3(DIM / 32, INNER / 32), dim3(32, 8)>>>(Wout, woT, INNER, DIM);

    // 3) q = ln @ Wq   (1024 x 1024 x 1024)
    gemm_bf16_kernel<<<dim3(INNER / 128, (BSZ * N2) / 128), 256, GT_SMEM>>>(
        ln, wqT, q, BSZ * N2, INNER, DIM);

    // 4) kv = xn @ Wkv (16384 x 2048 x 1024) — dominant GEMM
    gemm_bf16_kernel<<<dim3((2 * INNER) / 128, (BSZ * N1) / 128), 256, GT_SMEM>>>(
        xn, wkvT, kv, BSZ * N1, 2 * INNER, DIM);

    // 5) fused modulation + attention
    attn_kernel<<<dim3(BSZ * HEADS, N2 / 64), 256>>>(q, kv, shift, scale, ao);

    // 6) out = ao @ Wout (1024 x 1024 x 1024)
    gemm_bf16_kernel<<<dim3(DIM / 128, (BSZ * N2) / 128), 256, GT_SMEM>>>(
        ao, woT, out, BSZ * N2, DIM, INNER);
}

// round 7
// speedup vs baseline: 2.5871x; 1.2758x over previous
#include <cuda_runtime.h>
#include <cuda_bf16.h>
#include <cstdint>
#include <math.h>

// Problem constants
#define BSZ   4
#define N1    4096
#define N2    256
#define DIM   1024
#define HEADS 16
#define DH    64
#define INNER 1024
#define EPS   1e-5f

// ---------------------------------------------------------------------------
// Scratch (device globals; no runtime allocation allowed)
// ---------------------------------------------------------------------------
__device__ float g_xn[BSZ * N1 * DIM];          // 64 MB  : layernorm(x)
__device__ float g_ln[BSZ * N2 * DIM];          //  4 MB  : layernorm(latents)
__device__ float g_q [BSZ * N2 * INNER];        //  4 MB  : q = ln @ Wq
__device__ float g_kv[BSZ * N1 * 2 * INNER];    // 128 MB : kv = xn @ Wkv
__device__ float g_ao[BSZ * N2 * INNER];        //  4 MB  : attention output
__device__ float g_wqT [INNER * DIM];           //  4 MB  : Wq^T   [N,K]
__device__ float g_wkvT[2 * INNER * DIM];       //  8 MB  : Wkv^T  [N,K]
__device__ float g_woT [DIM * INNER];           //  4 MB  : Wout^T [N,K]

// ---------------------------------------------------------------------------
// MMA + packing helpers
// ---------------------------------------------------------------------------
__device__ __forceinline__ void mma_bf16(float* c, const uint32_t* a, const uint32_t* b) {
    asm volatile(
        "mma.sync.aligned.m16n8k16.row.col.f32.bf16.bf16.f32 "
        "{%0,%1,%2,%3}, {%4,%5,%6,%7}, {%8,%9}, {%0,%1,%2,%3};"
        : "+f"(c[0]), "+f"(c[1]), "+f"(c[2]), "+f"(c[3])
        : "r"(a[0]), "r"(a[1]), "r"(a[2]), "r"(a[3]), "r"(b[0]), "r"(b[1]));
}

__device__ __forceinline__ uint32_t pack_bf16(float x, float y) {
    __nv_bfloat162 h = __floats2bfloat162_rn(x, y);
    return *reinterpret_cast<uint32_t*>(&h);
}

// ---------------------------------------------------------------------------
// Block reduction helper (256 threads = 8 warps)
// ---------------------------------------------------------------------------
__device__ __forceinline__ float block_sum_256(float v, float* sbuf) {
    #pragma unroll
    for (int off = 16; off > 0; off >>= 1)
        v += __shfl_xor_sync(0xffffffffu, v, off);
    int w = threadIdx.x >> 5;
    if ((threadIdx.x & 31) == 0) sbuf[w] = v;
    __syncthreads();
    float r = (threadIdx.x < 8) ? sbuf[threadIdx.x] : 0.0f;
    #pragma unroll
    for (int off = 4; off > 0; off >>= 1)
        r += __shfl_xor_sync(0xffffffffu, r, off);
    if (threadIdx.x == 0) sbuf[0] = r;
    __syncthreads();
    float out = sbuf[0];
    __syncthreads();
    return out;
}

// ---------------------------------------------------------------------------
// LayerNorm over last dim (1024). One block per row, 256 threads, float4.
// ---------------------------------------------------------------------------
__global__ void ln_kernel(const float* __restrict__ x,
                          const float* __restrict__ w,
                          const float* __restrict__ b,
                          float* __restrict__ y) {
    __shared__ float sbuf[8];
    size_t row = blockIdx.x;
    int t = threadIdx.x;

    const float4 v = ((const float4*)(x + row * DIM))[t];
    float s = v.x + v.y + v.z + v.w;
    float tot = block_sum_256(s, sbuf);
    float mean = tot * (1.0f / DIM);

    float dx = v.x - mean, dy = v.y - mean, dz = v.z - mean, dw = v.w - mean;
    float sq = dx * dx + dy * dy + dz * dz + dw * dw;
    float vtot = block_sum_256(sq, sbuf);
    float inv = rsqrtf(vtot * (1.0f / DIM) + EPS);

    const float4 wv = ((const float4*)w)[t];
    const float4 bv = ((const float4*)b)[t];
    float4 o;
    o.x = dx * inv * wv.x + bv.x;
    o.y = dy * inv * wv.y + bv.y;
    o.z = dz * inv * wv.z + bv.z;
    o.w = dw * inv * wv.w + bv.w;
    ((float4*)(y + row * DIM))[t] = o;
}

// ---------------------------------------------------------------------------
// 32x32 tiled transpose: out[C,R] = in[R,C]^T  (R, C multiples of 32)
// ---------------------------------------------------------------------------
__global__ void transpose_kernel(const float* __restrict__ in,
                                 float* __restrict__ out, int R, int C) {
    __shared__ float t[32][33];
    int c0 = blockIdx.x * 32, r0 = blockIdx.y * 32;
    #pragma unroll
    for (int i = 0; i < 32; i += 8)
        t[threadIdx.y + i][threadIdx.x] =
            in[(size_t)(r0 + threadIdx.y + i) * C + c0 + threadIdx.x];
    __syncthreads();
    #pragma unroll
    for (int i = 0; i < 32; i += 8)
        out[(size_t)(c0 + threadIdx.y + i) * R + r0 + threadIdx.x] =
            t[threadIdx.x][threadIdx.y + i];
}

// ---------------------------------------------------------------------------
// bf16-split tensor-core GEMM: C[M,N] = A[M,K] @ Bt[N,K]^T  (fp32 accuracy)
// ---------------------------------------------------------------------------
#define RS 20                       // smem row stride in 32-bit words
#define MATW (128 * RS)             // 2560 words per matrix
#define GT_SMEM (4 * MATW * 4)      // 40960 bytes

__global__ void __launch_bounds__(256, 2)
gemm_bf16_kernel(const float* __restrict__ A, const float* __restrict__ Bt,
                 float* __restrict__ C, int M, int N, int K) {
    extern __shared__ uint32_t sh[];
    uint32_t* AH = sh;
    uint32_t* AL = sh + MATW;
    uint32_t* BH = sh + 2 * MATW;
    uint32_t* BL = sh + 3 * MATW;

    const int tid  = threadIdx.x;
    const int lane = tid & 31;
    const int wid  = tid >> 5;
    const int warp_m = wid >> 2;      // 0..1
    const int warp_n = wid & 3;       // 0..3
    const int bm = blockIdx.y * 128;
    const int bn = blockIdx.x * 128;

    const int matB = tid >> 7;
    const int lt   = tid & 127;
    const int lf   = lt & 7;
    const int lr0  = lt >> 3;
    const float* src = matB ? (Bt + (size_t)bn * K) : (A + (size_t)bm * K);
    uint32_t* dstH = matB ? BH : AH;
    uint32_t* dstL = matB ? BL : AL;

    float acc[4][4][4];
    #pragma unroll
    for (int i = 0; i < 4; i++)
        #pragma unroll
        for (int j = 0; j < 4; j++)
            #pragma unroll
            for (int k = 0; k < 4; k++) acc[i][j][k] = 0.0f;

    const int aoff0 = (warp_m * 64 + (lane >> 2)) * RS + (lane & 3);
    const int boff0 = (warp_n * 32 + (lane >> 2)) * RS + (lane & 3);

    for (int k0 = 0; k0 < K; k0 += 32) {
        __syncthreads();

        #pragma unroll
        for (int i = 0; i < 8; i++) {
            int row = lr0 + 16 * i;
            float4 v = *(const float4*)(src + (size_t)row * K + k0 + lf * 4);
            float hx = __bfloat162float(__float2bfloat16_rn(v.x));
            float hy = __bfloat162float(__float2bfloat16_rn(v.y));
            float hz = __bfloat162float(__float2bfloat16_rn(v.z));
            float hw = __bfloat162float(__float2bfloat16_rn(v.w));
            int w = row * RS + lf * 2;
            dstH[w]     = pack_bf16(hx, hy);
            dstH[w + 1] = pack_bf16(hz, hw);
            dstL[w]     = pack_bf16(v.x - hx, v.y - hy);
            dstL[w + 1] = pack_bf16(v.z - hz, v.w - hw);
        }
        __syncthreads();

        #pragma unroll
        for (int ks = 0; ks < 2; ks++) {
            uint32_t bh[4][2], bl[4][2];
            #pragma unroll
            for (int nb = 0; nb < 4; nb++) {
                int wb = boff0 + nb * 8 * RS + ks * 8;
                bh[nb][0] = BH[wb];     bh[nb][1] = BH[wb + 4];
                bl[nb][0] = BL[wb];     bl[nb][1] = BL[wb + 4];
            }
            #pragma unroll
            for (int ma = 0; ma < 4; ma++) {
                int wa = aoff0 + ma * 16 * RS + ks * 8;
                uint32_t ah[4], al[4];
                ah[0] = AH[wa];             ah[1] = AH[wa + 8 * RS];
                ah[2] = AH[wa + 4];         ah[3] = AH[wa + 8 * RS + 4];
                al[0] = AL[wa];             al[1] = AL[wa + 8 * RS];
                al[2] = AL[wa + 4];         al[3] = AL[wa + 8 * RS + 4];
                #pragma unroll
                for (int nb = 0; nb < 4; nb++) {
                    mma_bf16(acc[ma][nb], ah, bh[nb]);
                    mma_bf16(acc[ma][nb], ah, bl[nb]);
                    mma_bf16(acc[ma][nb], al, bh[nb]);
                }
            }
        }
    }

    #pragma unroll
    for (int ma = 0; ma < 4; ma++) {
        int row = bm + warp_m * 64 + ma * 16 + (lane >> 2);
        #pragma unroll
        for (int nb = 0; nb < 4; nb++) {
            int col = bn + warp_n * 32 + nb * 8 + (lane & 3) * 2;
            *(float2*)(C + (size_t)row * N + col) =
                make_float2(acc[ma][nb][0], acc[ma][nb][1]);
            *(float2*)(C + (size_t)(row + 8) * N + col) =
                make_float2(acc[ma][nb][2], acc[ma][nb][3]);
        }
    }
}

// ---------------------------------------------------------------------------
// Tensor-core flash attention per (b, h, 64-query tile).
// 8 warps: warp_m = wid>>1 owns 16 q-rows; warp_x = wid&1 owns a 32-wide
// key (for S) / d (for PV) slice. bf16 3-term split on both QK^T and P·V.
// SMEM word stride 36 -> bank = 4*row + col, conflict-free fragment access.
// ---------------------------------------------------------------------------
#define AST 36                          // word stride
#define AMAT (64 * AST)                 // 2304 words per 64-row matrix
#define A_KH 0
#define A_KL (AMAT)
#define A_VH (2 * AMAT)
#define A_VL (3 * AMAT)
#define A_PH (4 * AMAT)
#define A_PL (5 * AMAT)
#define A_RED (6 * AMAT)                // 256 floats (redmax 128, redsum 128)
#define ATT_SMEM ((6 * AMAT + 256) * 4) // 56320 bytes

__global__ void __launch_bounds__(256, 2)
attn_tc_kernel(const float* __restrict__ q,
               const float* __restrict__ kv,
               const float* __restrict__ shift,
               const float* __restrict__ scale,
               float* __restrict__ out) {
    extern __shared__ uint32_t ash[];
    float* redmax = (float*)(ash + A_RED);        // [4 wm][16 row][2 wx]
    float* redsum = redmax + 128;

    const int bh = blockIdx.x;
    const int b  = bh >> 4;
    const int h  = bh & 15;
    const int qt = blockIdx.y;

    const int tid  = threadIdx.x;
    const int lane = tid & 31;
    const int wid  = tid >> 5;
    const int wm   = wid >> 1;          // 0..3 : q-row group (16 rows)
    const int wx   = wid & 1;           // 0..1 : key/d half (32 wide)
    const int r    = lane >> 2;         // 0..7
    const int c    = lane & 3;          // 0..3

    const float sc = 1.0f + scale[b * HEADS + h];
    const float sh = shift[b * HEADS + h];
    const float qmul = 0.125f;          // 1/sqrt(64)

    // ---- load + modulate + split Q fragments (held in registers) ----
    uint32_t qh[4][4], ql[4][4];
    {
        int rowA = qt * 64 + wm * 16 + r;
        const float* qA = q + ((size_t)(b * N2 + rowA)) * INNER + h * DH;
        const float* qB = qA + (size_t)8 * INNER;
        #pragma unroll
        for (int ks = 0; ks < 4; ks++) {
            int d0 = ks * 16 + c * 2;
            #pragma unroll
            for (int half = 0; half < 2; half++) {      // 0: d0, 1: d0+8
                float2 vA = *(const float2*)(qA + d0 + half * 8);
                float2 vB = *(const float2*)(qB + d0 + half * 8);
                float ax = (vA.x * sc + sh) * qmul, ay = (vA.y * sc + sh) * qmul;
                float bx = (vB.x * sc + sh) * qmul, by = (vB.y * sc + sh) * qmul;
                float hax = __bfloat162float(__float2bfloat16_rn(ax));
                float hay = __bfloat162float(__float2bfloat16_rn(ay));
                float hbx = __bfloat162float(__float2bfloat16_rn(bx));
                float hby = __bfloat162float(__float2bfloat16_rn(by));
                qh[ks][half * 2 + 0] = pack_bf16(hax, hay);
                qh[ks][half * 2 + 1] = pack_bf16(hbx, hby);
                ql[ks][half * 2 + 0] = pack_bf16(ax - hax, ay - hay);
                ql[ks][half * 2 + 1] = pack_bf16(bx - hbx, by - hby);
            }
        }
    }

    float o[4][4];
    #pragma unroll
    for (int i = 0; i < 4; i++)
        #pragma unroll
        for (int j = 0; j < 4; j++) o[i][j] = 0.0f;
    float mA = -INFINITY, mB = -INFINITY, lA = 0.0f, lB = 0.0f;

    __nv_bfloat16* vhB = (__nv_bfloat16*)(ash + A_VH);
    __nv_bfloat16* vlB = (__nv_bfloat16*)(ash + A_VL);

    for (int kt = 0; kt < N1 / 64; kt++) {
        __syncthreads();   // (a) previous PV reads done

        // ---- load K/V tiles, split to bf16 hi/lo ----
        #pragma unroll
        for (int i = 0; i < 4; i++) {
            int idx = tid + 256 * i;            // 0..1023
            int key = idx >> 4;                 // 0..63
            int f4  = idx & 15;                 // 0..15 -> d0 = 4*f4
            const float* base = kv + ((size_t)(b * N1 + kt * 64 + key)) * (2 * INNER)
                                   + h * DH + f4 * 4;
            float4 kk = *(const float4*)base;
            float4 vv = *(const float4*)(base + INNER);
            // K: row-major [key][d-words]
            float hx = __bfloat162float(__float2bfloat16_rn(kk.x));
            float hy = __bfloat162float(__float2bfloat16_rn(kk.y));
            float hz = __bfloat162float(__float2bfloat16_rn(kk.z));
            float hw = __bfloat162float(__float2bfloat16_rn(kk.w));
            int w = key * AST + f4 * 2;
            ash[A_KH + w]     = pack_bf16(hx, hy);
            ash[A_KH + w + 1] = pack_bf16(hz, hw);
            ash[A_KL + w]     = pack_bf16(kk.x - hx, kk.y - hy);
            ash[A_KL + w + 1] = pack_bf16(kk.z - hz, kk.w - hw);
            // V: transposed [d][key] (halfword stores)
            float vf[4] = {vv.x, vv.y, vv.z, vv.w};
            #pragma unroll
            for (int j = 0; j < 4; j++) {
                int d = f4 * 4 + j;
                __nv_bfloat16 hv = __float2bfloat16_rn(vf[j]);
                vhB[72 * d + key] = hv;
                vlB[72 * d + key] = __float2bfloat16_rn(vf[j] - __bfloat162float(hv));
            }
        }
        __syncthreads();   // (b) tiles ready

        // ---- S = Qmod @ K^T : 16q x 32key per warp ----
        float s[4][4];
        #pragma unroll
        for (int i = 0; i < 4; i++)
            #pragma unroll
            for (int j = 0; j < 4; j++) s[i][j] = 0.0f;

        #pragma unroll
        for (int ks = 0; ks < 4; ks++) {
            #pragma unroll
            for (int atom = 0; atom < 4; atom++) {
                int keyrow = wx * 32 + atom * 8 + r;
                int w = keyrow * AST + c + ks * 8;
                uint32_t bh2[2] = {ash[A_KH + w], ash[A_KH + w + 4]};
                uint32_t bl2[2] = {ash[A_KL + w], ash[A_KL + w + 4]};
                mma_bf16(s[atom], qh[ks], bh2);
                mma_bf16(s[atom], qh[ks], bl2);
                mma_bf16(s[atom], ql[ks], bh2);
            }
        }

        // ---- online softmax ----
        float mxA = s[0][0], mxB = s[0][2];
        #pragma unroll
        for (int atom = 0; atom < 4; atom++) {
            mxA = fmaxf(mxA, fmaxf(s[atom][0], s[atom][1]));
            mxB = fmaxf(mxB, fmaxf(s[atom][2], s[atom][3]));
        }
        mxA = fmaxf(mxA, __shfl_xor_sync(0xffffffffu, mxA, 1));
        mxA = fmaxf(mxA, __shfl_xor_sync(0xffffffffu, mxA, 2));
        mxB = fmaxf(mxB, __shfl_xor_sync(0xffffffffu, mxB, 1));
        mxB = fmaxf(mxB, __shfl_xor_sync(0xffffffffu, mxB, 2));
        if (c == 0) {
            redmax[(wm * 16 + r) * 2 + wx] = mxA;
            redmax[(wm * 16 + r + 8) * 2 + wx] = mxB;
        }
        __syncthreads();   // (c)

        float mnA = fmaxf(mA, fmaxf(redmax[(wm * 16 + r) * 2],
                                    redmax[(wm * 16 + r) * 2 + 1]));
        float mnB = fmaxf(mB, fmaxf(redmax[(wm * 16 + r + 8) * 2],
                                    redmax[(wm * 16 + r + 8) * 2 + 1]));
        float alphaA = __expf(mA - mnA);
        float alphaB = __expf(mB - mnB);
        mA = mnA; mB = mnB;

        float sumA = 0.0f, sumB = 0.0f;
        #pragma unroll
        for (int atom = 0; atom < 4; atom++) {
            s[atom][0] = __expf(s[atom][0] - mnA);
            s[atom][1] = __expf(s[atom][1] - mnA);
            s[atom][2] = __expf(s[atom][2] - mnB);
            s[atom][3] = __expf(s[atom][3] - mnB);
            sumA += s[atom][0] + s[atom][1];
            sumB += s[atom][2] + s[atom][3];
        }
        sumA += __shfl_xor_sync(0xffffffffu, sumA, 1);
        sumA += __shfl_xor_sync(0xffffffffu, sumA, 2);
        sumB += __shfl_xor_sync(0xffffffffu, sumB, 1);
        sumB += __shfl_xor_sync(0xffffffffu, sumB, 2);
        if (c == 0) {
            redsum[(wm * 16 + r) * 2 + wx] = sumA;
            redsum[(wm * 16 + r + 8) * 2 + wx] = sumB;
        }

        // pack P -> smem (hi/lo), rescale O
        #pragma unroll
        for (int atom = 0; atom < 4; atom++) {
            int wpos = wx * 16 + atom * 4 + c;
            float p0 = s[atom][0], p1 = s[atom][1];
            float p2 = s[atom][2], p3 = s[atom][3];
            float h0 = __bfloat162float(__float2bfloat16_rn(p0));
            float h1 = __bfloat162float(__float2bfloat16_rn(p1));
            float h2 = __bfloat162float(__float2bfloat16_rn(p2));
            float h3 = __bfloat162float(__float2bfloat16_rn(p3));
            ash[A_PH + (wm * 16 + r) * AST + wpos]     = pack_bf16(h0, h1);
            ash[A_PH + (wm * 16 + r + 8) * AST + wpos] = pack_bf16(h2, h3);
            ash[A_PL + (wm * 16 + r) * AST + wpos]     = pack_bf16(p0 - h0, p1 - h1);
            ash[A_PL + (wm * 16 + r + 8) * AST + wpos] = pack_bf16(p2 - h2, p3 - h3);
            o[atom][0] *= alphaA; o[atom][1] *= alphaA;
            o[atom][2] *= alphaB; o[atom][3] *= alphaB;
        }
        __syncthreads();   // (d) sums + P ready

        lA = lA * alphaA + redsum[(wm * 16 + r) * 2] + redsum[(wm * 16 + r) * 2 + 1];
        lB = lB * alphaB + redsum[(wm * 16 + r + 8) * 2] + redsum[(wm * 16 + r + 8) * 2 + 1];

        // ---- O += P @ V : 16q x 32d per warp over 64 keys ----
        #pragma unroll
        for (int ks = 0; ks < 4; ks++) {
            int row0 = wm * 16 + r;
            int wb = ks * 8 + c;
            uint32_t ah2[4], al2[4];
            ah2[0] = ash[A_PH + row0 * AST + wb];
            ah2[1] = ash[A_PH + (row0 + 8) * AST + wb];
            ah2[2] = ash[A_PH + row0 * AST + wb + 4];
            ah2[3] = ash[A_PH + (row0 + 8) * AST + wb + 4];
            al2[0] = ash[A_PL + row0 * AST + wb];
            al2[1] = ash[A_PL + (row0 + 8) * AST + wb];
            al2[2] = ash[A_PL + row0 * AST + wb + 4];
            al2[3] = ash[A_PL + (row0 + 8) * AST + wb + 4];
            #pragma unroll
            for (int atom = 0; atom < 4; atom++) {
                int drow = wx * 32 + atom * 8 + r;
                int w = drow * AST + c + ks * 8;
                uint32_t bh2[2] = {ash[A_VH + w], ash[A_VH + w + 4]};
                uint32_t bl2[2] = {ash[A_VL + w], ash[A_VL + w + 4]};
                mma_bf16(o[atom], ah2, bh2);
                mma_bf16(o[atom], ah2, bl2);
                mma_bf16(o[atom], al2, bh2);
            }
        }
    }

    // ---- epilogue ----
    float invA = 1.0f / lA, invB = 1.0f / lB;
    int rowA = qt * 64 + wm * 16 + r;
    #pragma unroll
    for (int atom = 0; atom < 4; atom++) {
        int col = h * DH + wx * 32 + atom * 8 + c * 2;
        *(float2*)(out + ((size_t)(b * N2 + rowA)) * INNER + col) =
            make_float2(o[atom][0] * invA, o[atom][1] * invA);
        *(float2*)(out + ((size_t)(b * N2 + rowA + 8)) * INNER + col) =
            make_float2(o[atom][2] * invB, o[atom][3] * invB);
    }
}

// ---------------------------------------------------------------------------
// Launcher
// ---------------------------------------------------------------------------
extern "C" void kernel_launch(void* const* d_in, const int* in_sizes, int n_in,
                              void* d_out, int out_size) {
    const float* x       = (const float*)d_in[0];
    const float* latents = (const float*)d_in[1];
    const float* shift   = (const float*)d_in[2];
    const float* scale   = (const float*)d_in[3];
    const float* ln1_w   = (const float*)d_in[4];
    const float* ln1_b   = (const float*)d_in[5];
    const float* ln2_w   = (const float*)d_in[6];
    const float* ln2_b   = (const float*)d_in[7];
    const float* Wq      = (const float*)d_in[8];
    const float* Wkv     = (const float*)d_in[9];
    const float* Wout    = (const float*)d_in[10];
    float* out           = (float*)d_out;

    float *xn, *ln, *q, *kv, *ao, *wqT, *wkvT, *woT;
    cudaGetSymbolAddress((void**)&xn,   g_xn);
    cudaGetSymbolAddress((void**)&ln,   g_ln);
    cudaGetSymbolAddress((void**)&q,    g_q);
    cudaGetSymbolAddress((void**)&kv,   g_kv);
    cudaGetSymbolAddress((void**)&ao,   g_ao);
    cudaGetSymbolAddress((void**)&wqT,  g_wqT);
    cudaGetSymbolAddress((void**)&wkvT, g_wkvT);
    cudaGetSymbolAddress((void**)&woT,  g_woT);

    cudaFuncSetAttribute(attn_tc_kernel,
                         cudaFuncAttributeMaxDynamicSharedMemorySize, ATT_SMEM);

    // 1) LayerNorms
    ln_kernel<<<BSZ * N1, 256>>>(x, ln1_w, ln1_b, xn);
    ln_kernel<<<BSZ * N2, 256>>>(latents, ln2_w, ln2_b, ln);

    // 2) transpose weights -> [N,K] (K-contiguous "col-major B" operands)
    transpose_kernel<<<dim3(INNER / 32, DIM / 32), dim3(32, 8)>>>(Wq, wqT, DIM, INNER);
    transpose_kernel<<<dim3(2 * INNER / 32, DIM / 32), dim3(32, 8)>>>(Wkv, wkvT, DIM, 2 * INNER);
    transpose_kernel<<<dim3(DIM / 32, INNER / 32), dim3(32, 8)>>>(Wout, woT, INNER, DIM);

    // 3) q = ln @ Wq   (1024 x 1024 x 1024)
    gemm_bf16_kernel<<<dim3(INNER / 128, (BSZ * N2) / 128), 256, GT_SMEM>>>(
        ln, wqT, q, BSZ * N2, INNER, DIM);

    // 4) kv = xn @ Wkv (16384 x 2048 x 1024) — dominant GEMM
    gemm_bf16_kernel<<<dim3((2 * INNER) / 128, (BSZ * N1) / 128), 256, GT_SMEM>>>(
        xn, wkvT, kv, BSZ * N1, 2 * INNER, DIM);

    // 5) fused modulation + tensor-core flash attention
    attn_tc_kernel<<<dim3(BSZ * HEADS, N2 / 64), 256, ATT_SMEM>>>(q, kv, shift, scale, ao);

    // 6) out = ao @ Wout (1024 x 1024 x 1024)
    gemm_bf16_kernel<<<dim3(DIM / 128, (BSZ * N2) / 128), 256, GT_SMEM>>>(
        ao, woT, out, BSZ * N2, DIM, INNER);
}